// round 9
// baseline (speedup 1.0000x reference)
#include <cuda_runtime.h>
#include <math.h>
#include <stdint.h>

#define BB 2
#define SS 2048
#define DD 1024
#define HH 16
#define HD 64
#define BH (BB*HH)        // 32
#define MROWS (BB*SS)     // 4096

// ---------------- scratch (device globals; no allocations allowed) ----------
__device__ float g_q[BH * SS * HD];     // [bh][s][d]
__device__ float g_k[BH * SS * HD];
__device__ float g_v[BH * SS * HD];
__device__ float g_ctx[MROWS * DD];     // [b*s][h*64+d]
__device__ float g_proj[MROWS * DD];

// ---------------- helpers ----------------------------------------------------
// tf32 mma consumes fp32-layout registers, ignoring the low 13 mantissa bits.
// We feed raw fp32 (truncation) -> no cvt needed, cp.async-able tiles.
__device__ __forceinline__ void mma_tf32(float* c,
                                         uint32_t a0, uint32_t a1, uint32_t a2, uint32_t a3,
                                         uint32_t b0, uint32_t b1)
{
    asm volatile(
        "mma.sync.aligned.m16n8k8.row.col.f32.tf32.tf32.f32 "
        "{%0,%1,%2,%3}, {%4,%5,%6,%7}, {%8,%9}, {%0,%1,%2,%3};"
        : "+f"(c[0]), "+f"(c[1]), "+f"(c[2]), "+f"(c[3])
        : "r"(a0), "r"(a1), "r"(a2), "r"(a3), "r"(b0), "r"(b1));
}

__device__ __forceinline__ void cp16(float* smem_dst, const float* gmem_src) {
    uint32_t s = (uint32_t)__cvta_generic_to_shared(smem_dst);
    asm volatile("cp.async.cg.shared.global [%0], [%1], 16;" :: "r"(s), "l"(gmem_src) : "memory");
}
#define CP_COMMIT()  asm volatile("cp.async.commit_group;" ::: "memory")
#define CP_WAIT1()   asm volatile("cp.async.wait_group 1;" ::: "memory")
#define CP_WAIT0()   asm volatile("cp.async.wait_group 0;" ::: "memory")

// =============================================================================
// kernel 1: fused QKV projection (tf32 mma, cp.async double-buffered)
// 256 thr = 8 warps (4m x 2n). BM=128, BN=64, BK=32.
// =============================================================================
__global__ __launch_bounds__(256) void qkv_tc(
    const float* __restrict__ hs,
    const float* __restrict__ Wq, const float* __restrict__ bq,
    const float* __restrict__ Wk, const float* __restrict__ bk,
    const float* __restrict__ Wv, const float* __restrict__ bv)
{
    __shared__ float As[2][128 * 36];
    __shared__ float Bs[2][64 * 36];

    const int m0    = blockIdx.y * 128;
    const int nblk  = blockIdx.x;
    const int which = nblk >> 4;
    const int n0    = (nblk & 15) * 64;

    const float* Wp  = (which == 0) ? Wq : (which == 1 ? Wk : Wv);
    const float* bp  = (which == 0) ? bq : (which == 1 ? bk : bv);
    float*       dst = (which == 0) ? g_q : (which == 1 ? g_k : g_v);
    const float scale = (which == 0) ? 0.125f : 1.0f;

    const int tid = threadIdx.x;
    const int w = tid >> 5, lane = tid & 31;
    const int wm = w >> 1, wn = w & 1;
    const int gid = lane >> 2, tg = lane & 3;

    float acc[2][4][4];
#pragma unroll
    for (int t = 0; t < 2; t++)
#pragma unroll
        for (int j = 0; j < 4; j++)
#pragma unroll
            for (int e = 0; e < 4; e++) acc[t][j][e] = 0.f;

    // fill stage: A 128x32 (1024 16B-chunks), B 64x32 (512 chunks)
    auto fill = [&](int buf, int k0) {
#pragma unroll
        for (int i = 0; i < 4; i++) {
            int c = tid + i * 256;
            int r = c >> 3, cc = (c & 7) * 4;
            cp16(&As[buf][r * 36 + cc], &hs[(size_t)(m0 + r) * DD + k0 + cc]);
        }
#pragma unroll
        for (int i = 0; i < 2; i++) {
            int c = tid + i * 256;
            int r = c >> 3, cc = (c & 7) * 4;
            cp16(&Bs[buf][r * 36 + cc], &Wp[(size_t)(n0 + r) * DD + k0 + cc]);
        }
        CP_COMMIT();
    };

    fill(0, 0);

    for (int s = 0; s < 32; s++) {
        const int cur = s & 1;
        __syncthreads();                       // prev compute done reading buf cur^1
        if (s + 1 < 32) { fill(cur ^ 1, (s + 1) * 32); CP_WAIT1(); }
        else            { CP_WAIT0(); }
        __syncthreads();                       // buf cur fully landed (all threads)

#pragma unroll
        for (int kk = 0; kk < 4; kk++) {
            uint32_t a[2][4];
#pragma unroll
            for (int t = 0; t < 2; t++) {
                const float* ab = &As[cur][(wm * 32 + t * 16 + gid) * 36 + kk * 8 + tg];
                a[t][0] = __float_as_uint(ab[0]);
                a[t][1] = __float_as_uint(ab[8 * 36]);
                a[t][2] = __float_as_uint(ab[4]);
                a[t][3] = __float_as_uint(ab[8 * 36 + 4]);
            }
#pragma unroll
            for (int j = 0; j < 4; j++) {
                const float* bbp = &Bs[cur][(wn * 32 + j * 8 + gid) * 36 + kk * 8 + tg];
                uint32_t b0 = __float_as_uint(bbp[0]);
                uint32_t b1 = __float_as_uint(bbp[4]);
#pragma unroll
                for (int t = 0; t < 2; t++)
                    mma_tf32(acc[t][j], a[t][0], a[t][1], a[t][2], a[t][3], b0, b1);
            }
        }
    }

    // epilogue: +bias, *scale, scatter to [bh][s][d]
#pragma unroll
    for (int t = 0; t < 2; t++) {
#pragma unroll
        for (int j = 0; j < 4; j++) {
            int col = n0 + wn * 32 + j * 8 + 2 * tg;
            int h = col >> 6, d = col & 63;
            float b0v = bp[col], b1v = bp[col + 1];
#pragma unroll
            for (int rr = 0; rr < 2; rr++) {
                int m = m0 + wm * 32 + t * 16 + gid + rr * 8;
                int b = m >> 11, sidx = m & 2047;
                float2 o;
                o.x = (acc[t][j][rr * 2 + 0] + b0v) * scale;
                o.y = (acc[t][j][rr * 2 + 1] + b1v) * scale;
                *(float2*)&dst[(((size_t)(b * HH + h)) * SS + sidx) * HD + d] = o;
            }
        }
    }
}

// =============================================================================
// kernel 2: flash attention, tf32 mma, double-buffered cp.async K/V,
// register-prefetched extra+mask. 128 thr = 4 warps, 64 q-rows per block.
// =============================================================================
__global__ __launch_bounds__(128) void attn_tc(const float* __restrict__ extra,
                                               const float* __restrict__ mask)
{
    extern __shared__ float sm[];
    float* Qs = sm;                          // [64][68]
    float* Ks0 = Qs + 64 * 68;               // [2][64][68]
    float* Vs0 = Ks0 + 2 * 64 * 68;          // [2][64][72]
    float* Ps = Vs0 + 2 * 64 * 72;           // [64][68]

    const int bh = blockIdx.y, b = bh >> 4, h = bh & 15;
    const int q0 = blockIdx.x * 64;
    const int tid = threadIdx.x;
    const int w = tid >> 5, lane = tid & 31;
    const int gid = lane >> 2, tg = lane & 3;
    const int qr = w * 16 + gid;

    const float* erow = extra + ((size_t)bh * SS + q0 + qr) * SS;
    const float* mrow = mask  + ((size_t)b  * SS + q0 + qr) * SS;

    // prologue group G0: Q + K/V tile0
#pragma unroll
    for (int i = 0; i < 8; i++) {
        int c = tid + i * 128;
        int r = c >> 4, cc = (c & 15) * 4;
        cp16(&Qs[r * 68 + cc], &g_q[((size_t)bh * SS + q0 + r) * HD + cc]);
    }
    auto fill_kv = [&](int buf, int k0) {
        float* Kb = Ks0 + buf * 64 * 68;
        float* Vb = Vs0 + buf * 64 * 72;
#pragma unroll
        for (int i = 0; i < 8; i++) {
            int c = tid + i * 128;
            int r = c >> 4, cc = (c & 15) * 4;
            size_t g = ((size_t)bh * SS + k0 + r) * HD + cc;
            cp16(&Kb[r * 68 + cc], &g_k[g]);
            cp16(&Vb[r * 72 + cc], &g_v[g]);
        }
        CP_COMMIT();
    };
    fill_kv(0, 0);

    // prefetch extra+mask for tile 0
    float emn[8][4];
    auto load_em = [&](int k0) {
#pragma unroll
        for (int j = 0; j < 8; j++) {
            int c = k0 + j * 8 + 2 * tg;
            float2 e0 = *(const float2*)&erow[c];
            float2 mm0 = *(const float2*)&mrow[c];
            float2 e1 = *(const float2*)&erow[8 * SS + c];
            float2 mm1 = *(const float2*)&mrow[8 * SS + c];
            emn[j][0] = e0.x + mm0.x; emn[j][1] = e0.y + mm0.y;
            emn[j][2] = e1.x + mm1.x; emn[j][3] = e1.y + mm1.y;
        }
    };
    load_em(0);

    float oacc[8][4];
#pragma unroll
    for (int j = 0; j < 8; j++)
#pragma unroll
        for (int e = 0; e < 4; e++) oacc[j][e] = 0.f;
    float mi0 = -1e30f, mi1 = -1e30f, li0 = 0.f, li1 = 0.f;

    for (int kt = 0; kt < 32; kt++) {
        const int cur = kt & 1;
        __syncthreads();                       // prev iter done reading buf cur^1
        if (kt + 1 < 32) { fill_kv(cur ^ 1, (kt + 1) * 64); CP_WAIT1(); }
        else             { CP_WAIT0(); }
        __syncthreads();                       // buf cur landed for all threads

        const float* Kb = Ks0 + cur * 64 * 68;
        const float* Vb = Vs0 + cur * 64 * 72;

        // score accumulator initialized with prefetched extra+mask
        float sacc[8][4];
#pragma unroll
        for (int j = 0; j < 8; j++)
#pragma unroll
            for (int e = 0; e < 4; e++) sacc[j][e] = emn[j][e];

        // S += Q K^T
#pragma unroll
        for (int kk = 0; kk < 8; kk++) {
            const float* qb = &Qs[qr * 68 + kk * 8 + tg];
            uint32_t a0 = __float_as_uint(qb[0]);
            uint32_t a1 = __float_as_uint(qb[8 * 68]);
            uint32_t a2 = __float_as_uint(qb[4]);
            uint32_t a3 = __float_as_uint(qb[8 * 68 + 4]);
#pragma unroll
            for (int j = 0; j < 8; j++) {
                const float* kb = &Kb[(j * 8 + gid) * 68 + kk * 8 + tg];
                mma_tf32(sacc[j], a0, a1, a2, a3,
                         __float_as_uint(kb[0]), __float_as_uint(kb[4]));
            }
        }

        // kick off extra+mask loads for next tile (latency hides under softmax+PV)
        if (kt + 1 < 32) load_em((kt + 1) * 64);

        // online softmax (rows qr, qr+8; quad-shuffle over tg)
        float mx0 = -1e30f, mx1 = -1e30f;
#pragma unroll
        for (int j = 0; j < 8; j++) {
            mx0 = fmaxf(mx0, fmaxf(sacc[j][0], sacc[j][1]));
            mx1 = fmaxf(mx1, fmaxf(sacc[j][2], sacc[j][3]));
        }
#pragma unroll
        for (int off = 1; off < 4; off <<= 1) {
            mx0 = fmaxf(mx0, __shfl_xor_sync(0xffffffffu, mx0, off));
            mx1 = fmaxf(mx1, __shfl_xor_sync(0xffffffffu, mx1, off));
        }
        float mn0 = fmaxf(mi0, mx0), mn1 = fmaxf(mi1, mx1);
        float c0 = __expf(mi0 - mn0), c1 = __expf(mi1 - mn1);
        mi0 = mn0; mi1 = mn1;

        float rs0 = 0.f, rs1 = 0.f;
#pragma unroll
        for (int j = 0; j < 8; j++) {
            float p0 = __expf(sacc[j][0] - mn0);
            float p1 = __expf(sacc[j][1] - mn0);
            float p2 = __expf(sacc[j][2] - mn1);
            float p3 = __expf(sacc[j][3] - mn1);
            rs0 += p0 + p1; rs1 += p2 + p3;
            float2 s01, s23;
            s01.x = p0; s01.y = p1;
            s23.x = p2; s23.y = p3;
            *(float2*)&Ps[qr * 68 + j * 8 + 2 * tg] = s01;
            *(float2*)&Ps[(qr + 8) * 68 + j * 8 + 2 * tg] = s23;
        }
#pragma unroll
        for (int off = 1; off < 4; off <<= 1) {
            rs0 += __shfl_xor_sync(0xffffffffu, rs0, off);
            rs1 += __shfl_xor_sync(0xffffffffu, rs1, off);
        }
        li0 = li0 * c0 + rs0;
        li1 = li1 * c1 + rs1;
#pragma unroll
        for (int j = 0; j < 8; j++) {
            oacc[j][0] *= c0; oacc[j][1] *= c0;
            oacc[j][2] *= c1; oacc[j][3] *= c1;
        }
        __syncwarp();                          // Ps rows are warp-private

        // O += P V
#pragma unroll
        for (int kk = 0; kk < 8; kk++) {
            const float* pb = &Ps[qr * 68 + kk * 8 + tg];
            uint32_t a0 = __float_as_uint(pb[0]);
            uint32_t a1 = __float_as_uint(pb[8 * 68]);
            uint32_t a2 = __float_as_uint(pb[4]);
            uint32_t a3 = __float_as_uint(pb[8 * 68 + 4]);
#pragma unroll
            for (int j = 0; j < 8; j++) {
                uint32_t b0 = __float_as_uint(Vb[(kk * 8 + tg) * 72 + j * 8 + gid]);
                uint32_t b1 = __float_as_uint(Vb[(kk * 8 + tg + 4) * 72 + j * 8 + gid]);
                mma_tf32(oacc[j], a0, a1, a2, a3, b0, b1);
            }
        }
    }

    // epilogue: normalize, write [b*s][h*64+d]
    float inv0 = 1.f / li0, inv1 = 1.f / li1;
#pragma unroll
    for (int j = 0; j < 8; j++) {
        int d = j * 8 + 2 * tg;
        float2 o0, o1;
        o0.x = oacc[j][0] * inv0; o0.y = oacc[j][1] * inv0;
        o1.x = oacc[j][2] * inv1; o1.y = oacc[j][3] * inv1;
        *(float2*)&g_ctx[((size_t)(b * SS) + q0 + qr) * DD + h * HD + d] = o0;
        *(float2*)&g_ctx[((size_t)(b * SS) + q0 + qr + 8) * DD + h * HD + d] = o1;
    }
}

// =============================================================================
// kernel 3: output projection (tf32 mma, cp.async double-buffered)
// =============================================================================
__global__ __launch_bounds__(256) void proj_tc(const float* __restrict__ Wo,
                                               const float* __restrict__ bo)
{
    __shared__ float As[2][128 * 36];
    __shared__ float Bs[2][64 * 36];

    const int m0 = blockIdx.y * 128;
    const int n0 = blockIdx.x * 64;
    const int tid = threadIdx.x;
    const int w = tid >> 5, lane = tid & 31;
    const int wm = w >> 1, wn = w & 1;
    const int gid = lane >> 2, tg = lane & 3;

    float acc[2][4][4];
#pragma unroll
    for (int t = 0; t < 2; t++)
#pragma unroll
        for (int j = 0; j < 4; j++)
#pragma unroll
            for (int e = 0; e < 4; e++) acc[t][j][e] = 0.f;

    auto fill = [&](int buf, int k0) {
#pragma unroll
        for (int i = 0; i < 4; i++) {
            int c = tid + i * 256;
            int r = c >> 3, cc = (c & 7) * 4;
            cp16(&As[buf][r * 36 + cc], &g_ctx[(size_t)(m0 + r) * DD + k0 + cc]);
        }
#pragma unroll
        for (int i = 0; i < 2; i++) {
            int c = tid + i * 256;
            int r = c >> 3, cc = (c & 7) * 4;
            cp16(&Bs[buf][r * 36 + cc], &Wo[(size_t)(n0 + r) * DD + k0 + cc]);
        }
        CP_COMMIT();
    };

    fill(0, 0);

    for (int s = 0; s < 32; s++) {
        const int cur = s & 1;
        __syncthreads();
        if (s + 1 < 32) { fill(cur ^ 1, (s + 1) * 32); CP_WAIT1(); }
        else            { CP_WAIT0(); }
        __syncthreads();

#pragma unroll
        for (int kk = 0; kk < 4; kk++) {
            uint32_t a[2][4];
#pragma unroll
            for (int t = 0; t < 2; t++) {
                const float* ab = &As[cur][(wm * 32 + t * 16 + gid) * 36 + kk * 8 + tg];
                a[t][0] = __float_as_uint(ab[0]);
                a[t][1] = __float_as_uint(ab[8 * 36]);
                a[t][2] = __float_as_uint(ab[4]);
                a[t][3] = __float_as_uint(ab[8 * 36 + 4]);
            }
#pragma unroll
            for (int j = 0; j < 4; j++) {
                const float* bbp = &Bs[cur][(wn * 32 + j * 8 + gid) * 36 + kk * 8 + tg];
                uint32_t b0 = __float_as_uint(bbp[0]);
                uint32_t b1 = __float_as_uint(bbp[4]);
#pragma unroll
                for (int t = 0; t < 2; t++)
                    mma_tf32(acc[t][j], a[t][0], a[t][1], a[t][2], a[t][3], b0, b1);
            }
        }
    }

#pragma unroll
    for (int t = 0; t < 2; t++) {
#pragma unroll
        for (int j = 0; j < 4; j++) {
            int col = n0 + wn * 32 + j * 8 + 2 * tg;
            float b0v = bo[col], b1v = bo[col + 1];
#pragma unroll
            for (int rr = 0; rr < 2; rr++) {
                int m = m0 + wm * 32 + t * 16 + gid + rr * 8;
                float2 o;
                o.x = acc[t][j][rr * 2 + 0] + b0v;
                o.y = acc[t][j][rr * 2 + 1] + b1v;
                *(float2*)&g_proj[(size_t)m * DD + col] = o;
            }
        }
    }
}

// =============================================================================
// kernel 4: residual + LayerNorm (memory-bound, ~12us)
// =============================================================================
__global__ void ln_kernel(const float* __restrict__ hs,
                          const float* __restrict__ gamma,
                          const float* __restrict__ beta,
                          float* __restrict__ out)
{
    const int row = blockIdx.x;
    const int tid = threadIdx.x;
    __shared__ float sh_s[8], sh_s2[8];

    float x[4];
    float s = 0.f, s2 = 0.f;
#pragma unroll
    for (int i = 0; i < 4; i++) {
        int c = tid + i * 256;
        float v = hs[(size_t)row * DD + c] + g_proj[(size_t)row * DD + c];
        x[i] = v; s += v; s2 += v * v;
    }
#pragma unroll
    for (int off = 16; off; off >>= 1) {
        s  += __shfl_xor_sync(0xffffffffu, s,  off);
        s2 += __shfl_xor_sync(0xffffffffu, s2, off);
    }
    int w = tid >> 5, ln = tid & 31;
    if (ln == 0) { sh_s[w] = s; sh_s2[w] = s2; }
    __syncthreads();
    if (w == 0) {
        s  = (ln < 8) ? sh_s[ln]  : 0.f;
        s2 = (ln < 8) ? sh_s2[ln] : 0.f;
#pragma unroll
        for (int off = 4; off; off >>= 1) {
            s  += __shfl_xor_sync(0xffffffffu, s,  off);
            s2 += __shfl_xor_sync(0xffffffffu, s2, off);
        }
        if (ln == 0) { sh_s[0] = s; sh_s2[0] = s2; }
    }
    __syncthreads();
    float mu  = sh_s[0] * (1.f / DD);
    float var = sh_s2[0] * (1.f / DD) - mu * mu;
    float inv = rsqrtf(var + 1e-5f);
#pragma unroll
    for (int i = 0; i < 4; i++) {
        int c = tid + i * 256;
        out[(size_t)row * DD + c] = (x[i] - mu) * inv * gamma[c] + beta[c];
    }
}

// ---------------- launch -----------------------------------------------------
extern "C" void kernel_launch(void* const* d_in, const int* in_sizes, int n_in,
                              void* d_out, int out_size)
{
    const float* hs    = (const float*)d_in[0];
    const float* mask  = (const float*)d_in[1];
    const float* extra = (const float*)d_in[2];
    const float* Wq = (const float*)d_in[3];  const float* bq = (const float*)d_in[4];
    const float* Wk = (const float*)d_in[5];  const float* bk = (const float*)d_in[6];
    const float* Wv = (const float*)d_in[7];  const float* bv = (const float*)d_in[8];
    const float* Wo = (const float*)d_in[9];  const float* bo = (const float*)d_in[10];
    const float* gamma = (const float*)d_in[11];
    const float* beta  = (const float*)d_in[12];
    float* out = (float*)d_out;

    // 1) QKV projections
    dim3 g1(48, 32);
    qkv_tc<<<g1, 256>>>(hs, Wq, bq, Wk, bk, Wv, bv);

    // 2) flash attention: smem = (64*68 + 2*64*68 + 2*64*72 + 64*68)*4 = 106496 B
    const int smem = (64 * 68 + 2 * 64 * 68 + 2 * 64 * 72 + 64 * 68) * (int)sizeof(float);
    cudaFuncSetAttribute(attn_tc, cudaFuncAttributeMaxDynamicSharedMemorySize, smem);
    dim3 g2(SS / 64, BH);
    attn_tc<<<g2, 128, smem>>>(extra, mask);

    // 3) output projection
    dim3 g3(16, 32);
    proj_tc<<<g3, 256>>>(Wo, bo);

    // 4) residual + LayerNorm
    ln_kernel<<<MROWS, 256>>>(hs, gamma, beta, out);
}

// round 10
// speedup vs baseline: 1.6813x; 1.6813x over previous
#include <cuda_runtime.h>
#include <cuda_fp16.h>
#include <math.h>
#include <stdint.h>

#define BB 2
#define SS 2048
#define DD 1024
#define HH 16
#define HD 64
#define BH (BB*HH)        // 32
#define MROWS (BB*SS)     // 4096

// ---------------- scratch (device globals; no allocations allowed) ----------
__device__ __half g_qh[BH * SS * HD];    // [bh][s][d]   8 MB
__device__ __half g_kh[BH * SS * HD];    // [bh][s][d]
__device__ __half g_vT[BH * HD * SS];    // [bh][d][s]   (pre-transposed V)
__device__ __half g_ctxh[MROWS * DD];    // [b*s][h*64+d]
__device__ float  g_proj[MROWS * DD];    // fp32 attn_out (residual precision)

// ---------------- fp16 mma helper -------------------------------------------
__device__ __forceinline__ void mma_f16(float* c,
                                        uint32_t a0, uint32_t a1, uint32_t a2, uint32_t a3,
                                        uint32_t b0, uint32_t b1)
{
    asm volatile(
        "mma.sync.aligned.m16n8k16.row.col.f32.f16.f16.f32 "
        "{%0,%1,%2,%3}, {%4,%5,%6,%7}, {%8,%9}, {%0,%1,%2,%3};"
        : "+f"(c[0]), "+f"(c[1]), "+f"(c[2]), "+f"(c[3])
        : "r"(a0), "r"(a1), "r"(a2), "r"(a3), "r"(b0), "r"(b1));
}

__device__ __forceinline__ uint32_t h2u(__half2 h) { return *(uint32_t*)&h; }

// =============================================================================
// kernel 1: fused QKV projection (fp16 m16n8k16)
// 256 thr = 8 warps (4m x 2n). BM=128, BN=64, BK=32. Stride 56 halves (112B).
// =============================================================================
#define QSTR 56
__global__ __launch_bounds__(256) void qkv_tc(
    const float* __restrict__ hs,
    const float* __restrict__ Wq, const float* __restrict__ bq,
    const float* __restrict__ Wk, const float* __restrict__ bk,
    const float* __restrict__ Wv, const float* __restrict__ bv)
{
    __shared__ __half As[128 * QSTR];
    __shared__ __half Bs[64 * QSTR];

    const int m0    = blockIdx.y * 128;
    const int nblk  = blockIdx.x;
    const int which = nblk >> 4;             // 0=q 1=k 2=v
    const int n0    = (nblk & 15) * 64;

    const float* Wp = (which == 0) ? Wq : (which == 1 ? Wk : Wv);
    const float* bp = (which == 0) ? bq : (which == 1 ? bk : bv);
    const float scale = (which == 0) ? 0.125f : 1.0f;

    const int tid = threadIdx.x;
    const int w = tid >> 5, lane = tid & 31;
    const int wm = w >> 1, wn = w & 1;
    const int gid = lane >> 2, tg = lane & 3;

    float acc[2][4][4];
#pragma unroll
    for (int t = 0; t < 2; t++)
#pragma unroll
        for (int j = 0; j < 4; j++)
#pragma unroll
            for (int e = 0; e < 4; e++) acc[t][j][e] = 0.f;

    for (int k0 = 0; k0 < DD; k0 += 32) {
        __syncthreads();
        // A: 128x32 fp32 -> half
#pragma unroll
        for (int i = 0; i < 4; i++) {
            int idx = tid + i * 256;
            int r = idx >> 3, c = (idx & 7) * 4;
            float4 v = *(const float4*)&hs[(size_t)(m0 + r) * DD + k0 + c];
            uint2 p;
            p.x = h2u(__floats2half2_rn(v.x, v.y));
            p.y = h2u(__floats2half2_rn(v.z, v.w));
            *(uint2*)&As[r * QSTR + c] = p;
        }
        // B: 64x32 fp32 -> half
#pragma unroll
        for (int i = 0; i < 2; i++) {
            int idx = tid + i * 256;
            int r = idx >> 3, c = (idx & 7) * 4;
            float4 v = *(const float4*)&Wp[(size_t)(n0 + r) * DD + k0 + c];
            uint2 p;
            p.x = h2u(__floats2half2_rn(v.x, v.y));
            p.y = h2u(__floats2half2_rn(v.z, v.w));
            *(uint2*)&Bs[r * QSTR + c] = p;
        }
        __syncthreads();

#pragma unroll
        for (int kk = 0; kk < 2; kk++) {
            uint32_t a[2][4];
#pragma unroll
            for (int t = 0; t < 2; t++) {
                int ar = wm * 32 + t * 16 + gid;
                const __half* ab = &As[ar * QSTR + kk * 16 + 2 * tg];
                a[t][0] = *(const uint32_t*)&ab[0];
                a[t][1] = *(const uint32_t*)&ab[8 * QSTR];
                a[t][2] = *(const uint32_t*)&ab[8];
                a[t][3] = *(const uint32_t*)&ab[8 * QSTR + 8];
            }
#pragma unroll
            for (int j = 0; j < 4; j++) {
                int br = wn * 32 + j * 8 + gid;
                const __half* bb = &Bs[br * QSTR + kk * 16 + 2 * tg];
                uint32_t b0 = *(const uint32_t*)&bb[0];
                uint32_t b1 = *(const uint32_t*)&bb[8];
#pragma unroll
                for (int t = 0; t < 2; t++)
                    mma_f16(acc[t][j], a[t][0], a[t][1], a[t][2], a[t][3], b0, b1);
            }
        }
    }

    // epilogue: +bias, *scale, store fp16 to [bh][s][d] (q,k) or [bh][d][s] (v)
#pragma unroll
    for (int t = 0; t < 2; t++) {
#pragma unroll
        for (int j = 0; j < 4; j++) {
            int col = n0 + wn * 32 + j * 8 + 2 * tg;
            int h = col >> 6, d = col & 63;
            float b0v = bp[col], b1v = bp[col + 1];
#pragma unroll
            for (int rr = 0; rr < 2; rr++) {
                int m = m0 + wm * 32 + t * 16 + gid + rr * 8;
                int b = m >> 11, s = m & 2047;
                float vx = (acc[t][j][rr * 2 + 0] + b0v) * scale;
                float vy = (acc[t][j][rr * 2 + 1] + b1v) * scale;
                int bh = b * HH + h;
                if (which == 2) {
                    g_vT[((size_t)bh * HD + d) * SS + s]     = __float2half_rn(vx);
                    g_vT[((size_t)bh * HD + d + 1) * SS + s] = __float2half_rn(vy);
                } else {
                    __half* dst = (which == 0) ? g_qh : g_kh;
                    *(__half2*)&dst[((size_t)bh * SS + s) * HD + d] =
                        __floats2half2_rn(vx, vy);
                }
            }
        }
    }
}

// =============================================================================
// kernel 2: flash attention, fp16 m16n8k16.
// 128 thr = 4 warps, 64 q-rows/block, 32 k-tiles of 64. Smem 36KB static.
// =============================================================================
#define ASTR 72   // half stride (144B: 16B-aligned, conflict-free frag loads)
__global__ __launch_bounds__(128) void attn_tc(const float* __restrict__ extra,
                                               const float* __restrict__ mask)
{
    __shared__ __half Qs[64 * ASTR];
    __shared__ __half Ks[64 * ASTR];
    __shared__ __half Vt[64 * ASTR];   // [d][kv]
    __shared__ __half Ps[64 * ASTR];

    const int bh = blockIdx.y, b = bh >> 4, h = bh & 15;
    const int q0 = blockIdx.x * 64;
    const int tid = threadIdx.x;
    const int w = tid >> 5, lane = tid & 31;
    const int gid = lane >> 2, tg = lane & 3;
    const int qr = w * 16 + gid;

    // Q tile: 64x64 half, straight copy
#pragma unroll
    for (int i = 0; i < 4; i++) {
        int idx = tid + i * 128;
        int r = idx >> 3, c = (idx & 7) * 8;
        *(uint4*)&Qs[r * ASTR + c] =
            *(const uint4*)&g_qh[((size_t)bh * SS + q0 + r) * HD + c];
    }

    const float* erow = extra + ((size_t)bh * SS + q0 + qr) * SS;
    const float* mrow = mask  + ((size_t)b  * SS + q0 + qr) * SS;

    // prefetch extra+mask for tile 0
    float emn[8][4];
    auto load_em = [&](int k0) {
#pragma unroll
        for (int j = 0; j < 8; j++) {
            int c = k0 + j * 8 + 2 * tg;
            float2 e0 = *(const float2*)&erow[c];
            float2 mm0 = *(const float2*)&mrow[c];
            float2 e1 = *(const float2*)&erow[8 * SS + c];
            float2 mm1 = *(const float2*)&mrow[8 * SS + c];
            emn[j][0] = e0.x + mm0.x; emn[j][1] = e0.y + mm0.y;
            emn[j][2] = e1.x + mm1.x; emn[j][3] = e1.y + mm1.y;
        }
    };
    load_em(0);

    float oacc[8][4];
#pragma unroll
    for (int j = 0; j < 8; j++)
#pragma unroll
        for (int e = 0; e < 4; e++) oacc[j][e] = 0.f;
    float mi0 = -1e30f, mi1 = -1e30f, li0 = 0.f, li1 = 0.f;

    for (int kt = 0; kt < 32; kt++) {
        const int k0 = kt * 64;
        __syncthreads();                 // protect Ks/Vt overwrite (also orders Qs)
#pragma unroll
        for (int i = 0; i < 4; i++) {    // K: [kv][d],  Vt: [d][kv]
            int idx = tid + i * 128;
            int r = idx >> 3, c = (idx & 7) * 8;
            *(uint4*)&Ks[r * ASTR + c] =
                *(const uint4*)&g_kh[((size_t)bh * SS + k0 + r) * HD + c];
            *(uint4*)&Vt[r * ASTR + c] =
                *(const uint4*)&g_vT[((size_t)bh * HD + r) * SS + k0 + c];
        }
        __syncthreads();

        // S = extra+mask (prefetched) + Q K^T
        float sacc[8][4];
#pragma unroll
        for (int j = 0; j < 8; j++)
#pragma unroll
            for (int e = 0; e < 4; e++) sacc[j][e] = emn[j][e];

#pragma unroll
        for (int kk = 0; kk < 4; kk++) {
            const __half* qb = &Qs[qr * ASTR + kk * 16 + 2 * tg];
            uint32_t a0 = *(const uint32_t*)&qb[0];
            uint32_t a1 = *(const uint32_t*)&qb[8 * ASTR];
            uint32_t a2 = *(const uint32_t*)&qb[8];
            uint32_t a3 = *(const uint32_t*)&qb[8 * ASTR + 8];
#pragma unroll
            for (int j = 0; j < 8; j++) {
                const __half* kb = &Ks[(j * 8 + gid) * ASTR + kk * 16 + 2 * tg];
                mma_f16(sacc[j], a0, a1, a2, a3,
                        *(const uint32_t*)&kb[0], *(const uint32_t*)&kb[8]);
            }
        }

        // kick off next tile's extra+mask loads (hide ~600cyc under softmax+PV)
        if (kt + 1 < 32) load_em(k0 + 64);

        // online softmax (rows qr, qr+8; quad-shuffle over tg)
        float mx0 = -1e30f, mx1 = -1e30f;
#pragma unroll
        for (int j = 0; j < 8; j++) {
            mx0 = fmaxf(mx0, fmaxf(sacc[j][0], sacc[j][1]));
            mx1 = fmaxf(mx1, fmaxf(sacc[j][2], sacc[j][3]));
        }
#pragma unroll
        for (int off = 1; off < 4; off <<= 1) {
            mx0 = fmaxf(mx0, __shfl_xor_sync(0xffffffffu, mx0, off));
            mx1 = fmaxf(mx1, __shfl_xor_sync(0xffffffffu, mx1, off));
        }
        float mn0 = fmaxf(mi0, mx0), mn1 = fmaxf(mi1, mx1);
        float c0 = __expf(mi0 - mn0), c1 = __expf(mi1 - mn1);
        mi0 = mn0; mi1 = mn1;

        float rs0 = 0.f, rs1 = 0.f;
#pragma unroll
        for (int j = 0; j < 8; j++) {
            float p0 = __expf(sacc[j][0] - mn0);
            float p1 = __expf(sacc[j][1] - mn0);
            float p2 = __expf(sacc[j][2] - mn1);
            float p3 = __expf(sacc[j][3] - mn1);
            rs0 += p0 + p1; rs1 += p2 + p3;
            *(__half2*)&Ps[qr * ASTR + j * 8 + 2 * tg]       = __floats2half2_rn(p0, p1);
            *(__half2*)&Ps[(qr + 8) * ASTR + j * 8 + 2 * tg] = __floats2half2_rn(p2, p3);
        }
#pragma unroll
        for (int off = 1; off < 4; off <<= 1) {
            rs0 += __shfl_xor_sync(0xffffffffu, rs0, off);
            rs1 += __shfl_xor_sync(0xffffffffu, rs1, off);
        }
        li0 = li0 * c0 + rs0;
        li1 = li1 * c1 + rs1;
#pragma unroll
        for (int j = 0; j < 8; j++) {
            oacc[j][0] *= c0; oacc[j][1] *= c0;
            oacc[j][2] *= c1; oacc[j][3] *= c1;
        }
        __syncwarp();                    // Ps rows are warp-private

        // O += P V   (B = Vt[d][kv], kv-contiguous -> contiguous half2 frags)
#pragma unroll
        for (int kk = 0; kk < 4; kk++) {
            const __half* pb = &Ps[qr * ASTR + kk * 16 + 2 * tg];
            uint32_t a0 = *(const uint32_t*)&pb[0];
            uint32_t a1 = *(const uint32_t*)&pb[8 * ASTR];
            uint32_t a2 = *(const uint32_t*)&pb[8];
            uint32_t a3 = *(const uint32_t*)&pb[8 * ASTR + 8];
#pragma unroll
            for (int j = 0; j < 8; j++) {
                const __half* vb = &Vt[(j * 8 + gid) * ASTR + kk * 16 + 2 * tg];
                mma_f16(oacc[j], a0, a1, a2, a3,
                        *(const uint32_t*)&vb[0], *(const uint32_t*)&vb[8]);
            }
        }
    }

    // epilogue: normalize, store fp16 ctx [b*s][h*64+d]
    float inv0 = 1.f / li0, inv1 = 1.f / li1;
#pragma unroll
    for (int j = 0; j < 8; j++) {
        int d = j * 8 + 2 * tg;
        *(__half2*)&g_ctxh[((size_t)(b * SS) + q0 + qr) * DD + h * HD + d] =
            __floats2half2_rn(oacc[j][0] * inv0, oacc[j][1] * inv0);
        *(__half2*)&g_ctxh[((size_t)(b * SS) + q0 + qr + 8) * DD + h * HD + d] =
            __floats2half2_rn(oacc[j][2] * inv1, oacc[j][3] * inv1);
    }
}

// =============================================================================
// kernel 3: output projection (fp16 m16n8k16); A = fp16 ctx, B = Wo fp32->fp16
// =============================================================================
__global__ __launch_bounds__(256) void proj_tc(const float* __restrict__ Wo,
                                               const float* __restrict__ bo)
{
    __shared__ __half As[128 * QSTR];
    __shared__ __half Bs[64 * QSTR];

    const int m0 = blockIdx.y * 128;
    const int n0 = blockIdx.x * 64;
    const int tid = threadIdx.x;
    const int w = tid >> 5, lane = tid & 31;
    const int wm = w >> 1, wn = w & 1;
    const int gid = lane >> 2, tg = lane & 3;

    float acc[2][4][4];
#pragma unroll
    for (int t = 0; t < 2; t++)
#pragma unroll
        for (int j = 0; j < 4; j++)
#pragma unroll
            for (int e = 0; e < 4; e++) acc[t][j][e] = 0.f;

    for (int k0 = 0; k0 < DD; k0 += 32) {
        __syncthreads();
        // A: 128x32 half, straight copy (uint4 = 8 halves)
#pragma unroll
        for (int i = 0; i < 2; i++) {
            int idx = tid + i * 256;
            int r = idx >> 2, c = (idx & 3) * 8;
            *(uint4*)&As[r * QSTR + c] =
                *(const uint4*)&g_ctxh[(size_t)(m0 + r) * DD + k0 + c];
        }
        // B: 64x32 fp32 -> half
#pragma unroll
        for (int i = 0; i < 2; i++) {
            int idx = tid + i * 256;
            int r = idx >> 3, c = (idx & 7) * 4;
            float4 v = *(const float4*)&Wo[(size_t)(n0 + r) * DD + k0 + c];
            uint2 p;
            p.x = h2u(__floats2half2_rn(v.x, v.y));
            p.y = h2u(__floats2half2_rn(v.z, v.w));
            *(uint2*)&Bs[r * QSTR + c] = p;
        }
        __syncthreads();

#pragma unroll
        for (int kk = 0; kk < 2; kk++) {
            uint32_t a[2][4];
#pragma unroll
            for (int t = 0; t < 2; t++) {
                int ar = wm * 32 + t * 16 + gid;
                const __half* ab = &As[ar * QSTR + kk * 16 + 2 * tg];
                a[t][0] = *(const uint32_t*)&ab[0];
                a[t][1] = *(const uint32_t*)&ab[8 * QSTR];
                a[t][2] = *(const uint32_t*)&ab[8];
                a[t][3] = *(const uint32_t*)&ab[8 * QSTR + 8];
            }
#pragma unroll
            for (int j = 0; j < 4; j++) {
                int br = wn * 32 + j * 8 + gid;
                const __half* bb = &Bs[br * QSTR + kk * 16 + 2 * tg];
                uint32_t b0 = *(const uint32_t*)&bb[0];
                uint32_t b1 = *(const uint32_t*)&bb[8];
#pragma unroll
                for (int t = 0; t < 2; t++)
                    mma_f16(acc[t][j], a[t][0], a[t][1], a[t][2], a[t][3], b0, b1);
            }
        }
    }

#pragma unroll
    for (int t = 0; t < 2; t++) {
#pragma unroll
        for (int j = 0; j < 4; j++) {
            int col = n0 + wn * 32 + j * 8 + 2 * tg;
            float b0v = bo[col], b1v = bo[col + 1];
#pragma unroll
            for (int rr = 0; rr < 2; rr++) {
                int m = m0 + wm * 32 + t * 16 + gid + rr * 8;
                float2 o;
                o.x = acc[t][j][rr * 2 + 0] + b0v;
                o.y = acc[t][j][rr * 2 + 1] + b1v;
                *(float2*)&g_proj[(size_t)m * DD + col] = o;
            }
        }
    }
}

// =============================================================================
// kernel 4: residual + LayerNorm (memory-bound, ~11us)
// =============================================================================
__global__ void ln_kernel(const float* __restrict__ hs,
                          const float* __restrict__ gamma,
                          const float* __restrict__ beta,
                          float* __restrict__ out)
{
    const int row = blockIdx.x;
    const int tid = threadIdx.x;
    __shared__ float sh_s[8], sh_s2[8];

    float x[4];
    float s = 0.f, s2 = 0.f;
#pragma unroll
    for (int i = 0; i < 4; i++) {
        int c = tid + i * 256;
        float v = hs[(size_t)row * DD + c] + g_proj[(size_t)row * DD + c];
        x[i] = v; s += v; s2 += v * v;
    }
#pragma unroll
    for (int off = 16; off; off >>= 1) {
        s  += __shfl_xor_sync(0xffffffffu, s,  off);
        s2 += __shfl_xor_sync(0xffffffffu, s2, off);
    }
    int w = tid >> 5, ln = tid & 31;
    if (ln == 0) { sh_s[w] = s; sh_s2[w] = s2; }
    __syncthreads();
    if (w == 0) {
        s  = (ln < 8) ? sh_s[ln]  : 0.f;
        s2 = (ln < 8) ? sh_s2[ln] : 0.f;
#pragma unroll
        for (int off = 4; off; off >>= 1) {
            s  += __shfl_xor_sync(0xffffffffu, s,  off);
            s2 += __shfl_xor_sync(0xffffffffu, s2, off);
        }
        if (ln == 0) { sh_s[0] = s; sh_s2[0] = s2; }
    }
    __syncthreads();
    float mu  = sh_s[0] * (1.f / DD);
    float var = sh_s2[0] * (1.f / DD) - mu * mu;
    float inv = rsqrtf(var + 1e-5f);
#pragma unroll
    for (int i = 0; i < 4; i++) {
        int c = tid + i * 256;
        out[(size_t)row * DD + c] = (x[i] - mu) * inv * gamma[c] + beta[c];
    }
}

// ---------------- launch -----------------------------------------------------
extern "C" void kernel_launch(void* const* d_in, const int* in_sizes, int n_in,
                              void* d_out, int out_size)
{
    const float* hs    = (const float*)d_in[0];
    const float* mask  = (const float*)d_in[1];
    const float* extra = (const float*)d_in[2];
    const float* Wq = (const float*)d_in[3];  const float* bq = (const float*)d_in[4];
    const float* Wk = (const float*)d_in[5];  const float* bk = (const float*)d_in[6];
    const float* Wv = (const float*)d_in[7];  const float* bv = (const float*)d_in[8];
    const float* Wo = (const float*)d_in[9];  const float* bo = (const float*)d_in[10];
    const float* gamma = (const float*)d_in[11];
    const float* beta  = (const float*)d_in[12];
    float* out = (float*)d_out;

    // 1) QKV projections (fp16 mma, V stored transposed)
    dim3 g1(48, 32);
    qkv_tc<<<g1, 256>>>(hs, Wq, bq, Wk, bk, Wv, bv);

    // 2) flash attention (fp16 mma, 36KB static smem)
    dim3 g2(SS / 64, BH);
    attn_tc<<<g2, 128>>>(extra, mask);

    // 3) output projection
    dim3 g3(16, 32);
    proj_tc<<<g3, 256>>>(Wo, bo);

    // 4) residual + LayerNorm
    ln_kernel<<<MROWS, 256>>>(hs, gamma, beta, out);
}